// round 3
// baseline (speedup 1.0000x reference)
#include <cuda_runtime.h>

// GCN symmetric-normalized CSR aggregation.
// out[d,:] = rsqrt(deg[d]) * sum_{e in row d} rsqrt(deg[col[e]]) * feat[col[e],:]
//
// One warp per destination node.
//  - (src, rsqrt(deg[src])) for up to 32 edges loaded in parallel (one per
//    lane), broadcast per-edge via shfl.
//  - Warp split into 4 groups of 8 lanes; each group gathers a DIFFERENT
//    edge's 256B feature row as 8 lanes x 32B (2 x float4). With a 2x edge
//    unroll: 16 independent 128-bit gathers in flight per warp iteration.

#define FEAT 64
#define WARPS_PER_BLOCK 8
#define THREADS (WARPS_PER_BLOCK * 32)
#define FULL 0xffffffffu

__global__ __launch_bounds__(THREADS) void gcn_agg_kernel(
    const int* __restrict__ row_ptr,
    const int* __restrict__ col_idx,
    const float* __restrict__ node_feat,
    const float* __restrict__ degrees,
    float* __restrict__ out,
    int n_nodes)
{
    const int warp_id = (blockIdx.x * WARPS_PER_BLOCK) + (threadIdx.x >> 5);
    const int lane = threadIdx.x & 31;
    if (warp_id >= n_nodes) return;

    const int grp = lane >> 3;   // 0..3: which edge of the 4-group this lane works
    const int fl  = lane & 7;    // 32B slot within the 256B feature row

    const int start = __ldg(&row_ptr[warp_id]);
    const int deg   = __ldg(&row_ptr[warp_id + 1]) - start;

    // Two unroll streams x (2 float4) accumulators.
    float4 a0 = make_float4(0.f, 0.f, 0.f, 0.f);
    float4 b0 = make_float4(0.f, 0.f, 0.f, 0.f);
    float4 a1 = make_float4(0.f, 0.f, 0.f, 0.f);
    float4 b1 = make_float4(0.f, 0.f, 0.f, 0.f);

    for (int base = 0; base < deg; base += 32) {
        // Parallel batch load of up to 32 (src, norm) pairs — one per lane.
        const int mye = base + lane;
        int   s  = 0;
        float ns = 0.f;
        if (mye < deg) {
            s  = __ldg(&col_idx[start + mye]);
            ns = rsqrtf(__ldg(&degrees[s]));
        }
        const int cnt = min(32, deg - base);

        // 8 edges per iteration: groups take (j+grp) and (j+4+grp).
        for (int j = 0; j < cnt; j += 8) {
            const int jj0 = j + grp;          // <= 27, always a valid lane id
            const int jj1 = j + 4 + grp;      // <= 31, always a valid lane id
            const int   s0 = __shfl_sync(FULL, s,  jj0);
            const float n0 = __shfl_sync(FULL, ns, jj0);
            const int   s1 = __shfl_sync(FULL, s,  jj1);
            const float n1 = __shfl_sync(FULL, ns, jj1);

            if (jj0 < cnt) {
                const float4* p = (const float4*)(node_feat + (size_t)s0 * FEAT) + 2 * fl;
                const float4 va = __ldg(p);
                const float4 vb = __ldg(p + 1);
                a0.x = fmaf(n0, va.x, a0.x); a0.y = fmaf(n0, va.y, a0.y);
                a0.z = fmaf(n0, va.z, a0.z); a0.w = fmaf(n0, va.w, a0.w);
                b0.x = fmaf(n0, vb.x, b0.x); b0.y = fmaf(n0, vb.y, b0.y);
                b0.z = fmaf(n0, vb.z, b0.z); b0.w = fmaf(n0, vb.w, b0.w);
            }
            if (jj1 < cnt) {
                const float4* p = (const float4*)(node_feat + (size_t)s1 * FEAT) + 2 * fl;
                const float4 va = __ldg(p);
                const float4 vb = __ldg(p + 1);
                a1.x = fmaf(n1, va.x, a1.x); a1.y = fmaf(n1, va.y, a1.y);
                a1.z = fmaf(n1, va.z, a1.z); a1.w = fmaf(n1, va.w, a1.w);
                b1.x = fmaf(n1, vb.x, b1.x); b1.y = fmaf(n1, vb.y, b1.y);
                b1.z = fmaf(n1, vb.z, b1.z); b1.w = fmaf(n1, vb.w, b1.w);
            }
        }
    }

    // Merge unroll streams.
    a0.x += a1.x; a0.y += a1.y; a0.z += a1.z; a0.w += a1.w;
    b0.x += b1.x; b0.y += b1.y; b0.z += b1.z; b0.w += b1.w;

    // Fold the 4 groups together (lanes with equal fl share a feature slot).
    #pragma unroll
    for (int off = 8; off <= 16; off <<= 1) {
        a0.x += __shfl_xor_sync(FULL, a0.x, off);
        a0.y += __shfl_xor_sync(FULL, a0.y, off);
        a0.z += __shfl_xor_sync(FULL, a0.z, off);
        a0.w += __shfl_xor_sync(FULL, a0.w, off);
        b0.x += __shfl_xor_sync(FULL, b0.x, off);
        b0.y += __shfl_xor_sync(FULL, b0.y, off);
        b0.z += __shfl_xor_sync(FULL, b0.z, off);
        b0.w += __shfl_xor_sync(FULL, b0.w, off);
    }

    if (grp == 0) {
        const float nd = rsqrtf(__ldg(&degrees[warp_id]));
        float4 ra, rb;
        ra.x = a0.x * nd; ra.y = a0.y * nd; ra.z = a0.z * nd; ra.w = a0.w * nd;
        rb.x = b0.x * nd; rb.y = b0.y * nd; rb.z = b0.z * nd; rb.w = b0.w * nd;
        float4* po = (float4*)out + (size_t)warp_id * (FEAT / 4) + 2 * fl;
        po[0] = ra;
        po[1] = rb;
    }
}

extern "C" void kernel_launch(void* const* d_in, const int* in_sizes, int n_in,
                              void* d_out, int out_size)
{
    const int*   row_ptr   = (const int*)d_in[0];
    const int*   col_idx   = (const int*)d_in[1];
    const float* node_feat = (const float*)d_in[2];
    const float* degrees   = (const float*)d_in[3];
    float* out = (float*)d_out;

    const int n_nodes = in_sizes[0] - 1;
    const int blocks = (n_nodes + WARPS_PER_BLOCK - 1) / WARPS_PER_BLOCK;
    gcn_agg_kernel<<<blocks, THREADS>>>(row_ptr, col_idx, node_feat, degrees,
                                        out, n_nodes);
}

// round 4
// speedup vs baseline: 1.0402x; 1.0402x over previous
#include <cuda_runtime.h>

// GCN symmetric-normalized CSR aggregation.
// out[d,:] = rsqrt(deg[d]) * sum_{e in row d} rsqrt(deg[col[e]]) * feat[col[e],:]
//
// One warp per destination node, lane owns a float2 slice of the feature row.
// Per 32-edge batch: (src, rsqrt(deg[src])) pairs are loaded in parallel
// (one per lane) and staged in shared memory; the inner loop replays them
// with uniform LDS.64 broadcasts. Per edge the warp executes just
// LDS.64 + LDG.64 + 2 FMA, unrolled x4 with independent accumulators.

#define FEAT 64
#define WARPS_PER_BLOCK 8
#define THREADS (WARPS_PER_BLOCK * 32)
#define FULL 0xffffffffu

__global__ __launch_bounds__(THREADS) void gcn_agg_kernel(
    const int* __restrict__ row_ptr,
    const int* __restrict__ col_idx,
    const float* __restrict__ node_feat,
    const float* __restrict__ degrees,
    float* __restrict__ out,
    int n_nodes)
{
    __shared__ int2 sm_pairs[WARPS_PER_BLOCK][32];

    const int wslot   = threadIdx.x >> 5;
    const int warp_id = blockIdx.x * WARPS_PER_BLOCK + wslot;
    const int lane    = threadIdx.x & 31;
    if (warp_id >= n_nodes) return;

    const int start = __ldg(&row_ptr[warp_id]);
    const int deg   = __ldg(&row_ptr[warp_id + 1]) - start;

    float2 acc0 = make_float2(0.f, 0.f);
    float2 acc1 = make_float2(0.f, 0.f);
    float2 acc2 = make_float2(0.f, 0.f);
    float2 acc3 = make_float2(0.f, 0.f);

    const float2* __restrict__ featv = (const float2*)node_feat;

    for (int base = 0; base < deg; base += 32) {
        // Parallel batch: one (src, rsqrt(deg[src])) pair per lane.
        const int mye = base + lane;
        int   s  = 0;
        float ns = 0.f;
        if (mye < deg) {
            s  = __ldg(&col_idx[start + mye]);
            ns = rsqrtf(__ldg(&degrees[s]));
        }
        sm_pairs[wslot][lane] = make_int2(s, __float_as_int(ns));
        __syncwarp();

        const int cnt = min(32, deg - base);
        int j = 0;
        for (; j + 4 <= cnt; j += 4) {
            const int2 p0 = sm_pairs[wslot][j + 0];
            const int2 p1 = sm_pairs[wslot][j + 1];
            const int2 p2 = sm_pairs[wslot][j + 2];
            const int2 p3 = sm_pairs[wslot][j + 3];

            const float2 v0 = __ldg(featv + (size_t)p0.x * (FEAT / 2) + lane);
            const float2 v1 = __ldg(featv + (size_t)p1.x * (FEAT / 2) + lane);
            const float2 v2 = __ldg(featv + (size_t)p2.x * (FEAT / 2) + lane);
            const float2 v3 = __ldg(featv + (size_t)p3.x * (FEAT / 2) + lane);

            const float n0 = __int_as_float(p0.y);
            const float n1 = __int_as_float(p1.y);
            const float n2 = __int_as_float(p2.y);
            const float n3 = __int_as_float(p3.y);

            acc0.x = fmaf(n0, v0.x, acc0.x); acc0.y = fmaf(n0, v0.y, acc0.y);
            acc1.x = fmaf(n1, v1.x, acc1.x); acc1.y = fmaf(n1, v1.y, acc1.y);
            acc2.x = fmaf(n2, v2.x, acc2.x); acc2.y = fmaf(n2, v2.y, acc2.y);
            acc3.x = fmaf(n3, v3.x, acc3.x); acc3.y = fmaf(n3, v3.y, acc3.y);
        }
        for (; j < cnt; ++j) {
            const int2 p = sm_pairs[wslot][j];
            const float2 v = __ldg(featv + (size_t)p.x * (FEAT / 2) + lane);
            const float n = __int_as_float(p.y);
            acc0.x = fmaf(n, v.x, acc0.x);
            acc0.y = fmaf(n, v.y, acc0.y);
        }
        __syncwarp();
    }

    acc0.x += acc1.x; acc0.y += acc1.y;
    acc2.x += acc3.x; acc2.y += acc3.y;
    acc0.x += acc2.x; acc0.y += acc2.y;

    const float nd = rsqrtf(__ldg(&degrees[warp_id]));
    float2 r;
    r.x = acc0.x * nd;
    r.y = acc0.y * nd;
    ((float2*)out)[(size_t)warp_id * (FEAT / 2) + lane] = r;
}

extern "C" void kernel_launch(void* const* d_in, const int* in_sizes, int n_in,
                              void* d_out, int out_size)
{
    const int*   row_ptr   = (const int*)d_in[0];
    const int*   col_idx   = (const int*)d_in[1];
    const float* node_feat = (const float*)d_in[2];
    const float* degrees   = (const float*)d_in[3];
    float* out = (float*)d_out;

    const int n_nodes = in_sizes[0] - 1;
    const int blocks = (n_nodes + WARPS_PER_BLOCK - 1) / WARPS_PER_BLOCK;
    gcn_agg_kernel<<<blocks, THREADS>>>(row_ptr, col_idx, node_feat, degrees,
                                        out, n_nodes);
}